// round 5
// baseline (speedup 1.0000x reference)
#include <cuda_runtime.h>
#include <cstdint>

#define N_SESS   8192
#define N_TRIALS 1024
#define N_HALF   64            // 1024 / 16 steps per code word

// 2-bit codes (c<<1 | o), 16 steps per word, time-major: g_code[half*N_SESS + sess]
__device__ unsigned g_code[N_HALF * N_SESS];

// ---------------------------------------------------------------------------
// bit spread: bit j -> bit 2j (16-bit -> 32-bit)
// ---------------------------------------------------------------------------
__device__ __forceinline__ unsigned part16(unsigned v)
{
    v &= 0xFFFFu;
    v = (v | (v << 8)) & 0x00FF00FFu;
    v = (v | (v << 4)) & 0x0F0F0F0Fu;
    v = (v | (v << 2)) & 0x33333333u;
    v = (v | (v << 1)) & 0x55555555u;
    return v;
}

// ---------------------------------------------------------------------------
// Pack kernel: fully coalesced. Block = one session (3072 floats = 12 KB).
// Warp w covers 128 trials; lane loads 3 float4 (4 trials, 48 B contiguous).
// Emits 2-bit code words (16 trials each), time-major.
// ---------------------------------------------------------------------------
__global__ __launch_bounds__(256) void pack_kernel(const float* __restrict__ in)
{
    __shared__ unsigned shc[256], sho[256];
    const int lane = threadIdx.x & 31;
    const int warp = threadIdx.x >> 5;     // 128-trial group, 0..7
    const int s    = blockIdx.x;           // session

    const float4* p = reinterpret_cast<const float4*>(
        in + (size_t)s * 3072 + warp * 384 + lane * 12);
    float4 v0 = p[0], v1 = p[1], v2 = p[2];

    // trial j in lane's 4: c at {v0.x, v0.w, v1.z, v2.y}, o at {v0.z, v1.y, v2.x, v2.w}
    unsigned nc = (unsigned)(v0.x > 0.5f)        | ((unsigned)(v0.w > 0.5f) << 1)
                | ((unsigned)(v1.z > 0.5f) << 2) | ((unsigned)(v2.y > 0.5f) << 3);
    unsigned no = (unsigned)(v0.z > 0.5f)        | ((unsigned)(v1.y > 0.5f) << 1)
                | ((unsigned)(v2.x > 0.5f) << 2) | ((unsigned)(v2.w > 0.5f) << 3);
    shc[threadIdx.x] = nc;
    sho[threadIdx.x] = no;
    __syncwarp();

    if (lane < 4) {                         // each handles one 32-trial tile
        int base = warp * 32 + lane * 8;
        unsigned mc = 0, mo = 0;
        #pragma unroll
        for (int q = 0; q < 8; ++q) {
            mc |= shc[base + q] << (4 * q);
            mo |= sho[base + q] << (4 * q);
        }
        int tile32 = warp * 4 + lane;
        #pragma unroll
        for (int half = 0; half < 2; ++half) {
            unsigned cm16 = (mc >> (16 * half)) & 0xFFFFu;
            unsigned om16 = (mo >> (16 * half)) & 0xFFFFu;
            unsigned wrd  = part16(om16) | (part16(cm16) << 1);
            g_code[(tile32 * 2 + half) * N_SESS + s] = wrd;
        }
    }
}

// ---------------------------------------------------------------------------
// smooth_clamp(x,0,1), beta=100: single ex2.approx + deg-4 poly (abs err ~1e-6)
// ---------------------------------------------------------------------------
__device__ __forceinline__ float fast_clamp01(float x)
{
    float t  = x - 0.5f;
    float at = __int_as_float(__float_as_int(t) & 0x7fffffff);
    float w  = fmaf(at, -144.26950408889634f, 72.13475204444817f);
    float nw = __int_as_float(__float_as_int(w) | 0x80000000);   // -|w|
    float m  = fmaxf(w, 0.0f);
    float e;
    asm("ex2.approx.f32 %0, %1;" : "=f"(e) : "f"(nw));
    float e2   = e * e;
    float base = fmaf(m, 6.931471805599453e-3f, 1.4882e-6f);
    float low  = fmaf(9.9627e-3f, e, base);
    float hi   = fmaf(-5.5457e-4f, e, 2.1866e-3f);
    hi         = fmaf(hi, e, -4.6644e-3f);
    float sp   = fmaf(hi, e2, low);
    return (x < 0.5f) ? sp : 1.0f - sp;
}

// ---------------------------------------------------------------------------
// 16-step half-tile: pair-thread (even lane = L side, odd lane = R side).
// Both lanes keep QL,QR,alpha; each does ONE lambda clamp, shfl-exchanged.
// ---------------------------------------------------------------------------
template<bool FIRST>
__device__ __forceinline__ void do_half(
    unsigned cw,
    float& QL, float& QR, float& lamL, float& lamR, float& alpha,
    bool isL, int side, float* __restrict__ srow,
    const float4* __restrict__ tabC, const float* __restrict__ tabG,
    const float* __restrict__ tabF)
{
    #pragma unroll
    for (int i = 0; i < 16; ++i) {
        const int  code = (int)((cw >> (2 * i)) & 3u);
        const bool c    = (code & 2) != 0;
        const float4 tC = tabC[code];          // {kL, kR, gaS, C=gaS*a0S}
        const float glM = tabG[code * 2 + side];

        // alpha chain
        float u01  = c ? tC.x : tC.y;
        float QS   = c ? QL   : QR;
        float lamS = c ? lamL : lamR;
        float an;
        if (FIRST && i == 0) {
            an = tabF[code];                   // t==0: alpha_first
        } else {
            float p1 = fabsf(u01 - QS) - lamS;
            float p2 = p1 - alpha;
            float xa = fmaf(tC.z, p2, alpha) + tC.w;
            an = fast_clamp01(xa);
        }

        // per-side diffs (signed, shared with Q updates)
        float diffL = tC.x - QL;
        float diffR = tC.y - QR;

        // own-side lambda clamp, partner's via shfl (off critical chain)
        float dM     = isL ? diffL : diffR;
        float lamM   = isL ? lamL  : lamR;
        float lamArg = fmaf(glM, fabsf(dM) - lamM, lamM);
        float lamMn  = fast_clamp01(lamArg);
        float lamP   = __shfl_xor_sync(0xffffffffu, lamMn, 1);

        // Q updates with OLD lambdas, NEW alpha
        QL = fmaf(an, (1.0f - lamL) * diffL, QL);
        QR = fmaf(an, (1.0f - lamR) * diffR, QR);

        lamL  = isL ? lamMn : lamP;
        lamR  = isL ? lamP  : lamMn;
        alpha = an;

        srow[2 * i] = isL ? QL : QR;           // own-side value into staging row
    }
}

// ---------------------------------------------------------------------------
// Main scan: 2 threads per session (16 sessions/warp), 1024 serial steps.
// block=128 -> 4 warps on SMSP 0..3; grid=128 -> 512 busy SMSPs, 1 warp each.
// ---------------------------------------------------------------------------
__global__ __launch_bounds__(128, 1)
void agent_kernel(const float* __restrict__ a0p, const float* __restrict__ gap,
                  const float* __restrict__ glp, const float* __restrict__ kvp,
                  float4* __restrict__ out4)
{
    __shared__ float4 tabC[4];                       // {kL, kR, gaS, C}
    __shared__ float  tabG[8];                       // gl[code][side]
    __shared__ float  tabF[4];                       // alpha_first[code]
    __shared__ __align__(16) float tile[4][16][36];  // 16 sessions x 16 float2 (+pad)

    if (threadIdx.x < 4) {
        int code = threadIdx.x;
        int c = code >> 1, o = code & 1;
        float u01 = o ? kvp[0] : kvp[1];
        float u23 = o ? kvp[2] : kvp[3];
        float kL  = c ? u01 : u23;
        float kR  = c ? u23 : u01;
        float gl01 = o ? glp[0] : glp[1];
        float gl23 = o ? glp[2] : glp[3];
        float glL  = c ? gl01 : gl23;
        float glR  = c ? gl23 : gl01;
        float gaS  = c ? (o ? gap[0] : gap[1]) : (o ? gap[2] : gap[3]);
        float a0S  = o ? a0p[0] : a0p[1];
        float af   = c ? (o ? a0p[0] : a0p[1]) : (o ? a0p[2] : a0p[3]);
        tabC[code] = make_float4(kL, kR, gaS, gaS * a0S);
        tabG[code * 2 + 0] = glL;
        tabG[code * 2 + 1] = glR;
        tabF[code] = af;
    }
    __syncthreads();

    const int lane  = threadIdx.x & 31;
    const int warp  = threadIdx.x >> 5;
    const int warpg = blockIdx.x * 4 + warp;
    const int row   = lane >> 1;                 // session within warp, 0..15
    const int sess  = warpg * 16 + row;
    const int side  = lane & 1;                  // 0 = L, 1 = R
    const bool isL  = (side == 0);
    float* srow = &tile[warp][row][side];

    float QL = 0.0f, QR = 0.0f;
    float lamL = 0.5f, lamR = 0.5f, alpha = 0.0f;

    const size_t obase = (size_t)warpg * 16;     // first session row of this warp

    unsigned cw = g_code[sess];

    for (int h = 0; h < N_HALF; ++h) {
        unsigned cwn = (h + 1 < N_HALF) ? g_code[(h + 1) * N_SESS + sess] : 0u;

        if (h == 0)
            do_half<true >(cw, QL, QR, lamL, lamR, alpha, isL, side, srow, tabC, tabG, tabF);
        else
            do_half<false>(cw, QL, QR, lamL, lamR, alpha, isL, side, srow, tabC, tabG, tabF);

        __syncwarp();
        // flush 16 sessions x 8 float4 (32 floats each), coalesced 128-bit stores
        #pragma unroll
        for (int q = 0; q < 4; ++q) {
            int idx = q * 32 + lane;             // 0..127
            int r   = idx >> 3;                  // session row 0..15
            int col = idx & 7;                   // float4 col 0..7
            float4 v = *reinterpret_cast<const float4*>(&tile[warp][r][col * 4]);
            out4[(obase + r) * (N_TRIALS / 2) + (size_t)h * 8 + col] = v;
        }
        __syncwarp();

        cw = cwn;
    }
}

// ---------------------------------------------------------------------------
extern "C" void kernel_launch(void* const* d_in, const int* in_sizes, int n_in,
                              void* d_out, int out_size)
{
    (void)in_sizes; (void)n_in; (void)out_size;
    const float* input = (const float*)d_in[0];
    const float* a0    = (const float*)d_in[1];
    const float* ga    = (const float*)d_in[2];
    const float* gl    = (const float*)d_in[3];
    const float* kv    = (const float*)d_in[4];
    float4* out4 = (float4*)d_out;

    pack_kernel<<<N_SESS, 256>>>(input);
    // 16384 threads: 2 per session
    agent_kernel<<<128, 128>>>(a0, ga, gl, kv, out4);
}

// round 6
// speedup vs baseline: 1.3376x; 1.3376x over previous
#include <cuda_runtime.h>
#include <cstdint>

#define N_SESS   8192
#define N_TRIALS 1024
#define N_TILES  32

// Packed masks, tile-major: mask[tile*N_SESS + session]
__device__ unsigned g_cmask[N_TILES * N_SESS];
__device__ unsigned g_omask[N_TILES * N_SESS];

// ---------------------------------------------------------------------------
// Pack kernel (known good from R4): fully coalesced, block = one session.
// ---------------------------------------------------------------------------
__global__ __launch_bounds__(256) void pack_kernel(const float* __restrict__ in)
{
    __shared__ unsigned shc[256], sho[256];
    const int lane = threadIdx.x & 31;
    const int warp = threadIdx.x >> 5;     // 128-trial group, 0..7
    const int s    = blockIdx.x;           // session

    const float4* p = reinterpret_cast<const float4*>(
        in + (size_t)s * 3072 + warp * 384 + lane * 12);
    float4 v0 = p[0], v1 = p[1], v2 = p[2];

    unsigned nc = (unsigned)(v0.x > 0.5f)        | ((unsigned)(v0.w > 0.5f) << 1)
                | ((unsigned)(v1.z > 0.5f) << 2) | ((unsigned)(v2.y > 0.5f) << 3);
    unsigned no = (unsigned)(v0.z > 0.5f)        | ((unsigned)(v1.y > 0.5f) << 1)
                | ((unsigned)(v2.x > 0.5f) << 2) | ((unsigned)(v2.w > 0.5f) << 3);
    shc[threadIdx.x] = nc;
    sho[threadIdx.x] = no;
    __syncwarp();

    if (lane < 4) {
        int base = warp * 32 + lane * 8;
        unsigned mc = 0, mo = 0;
        #pragma unroll
        for (int q = 0; q < 8; ++q) {
            mc |= shc[base + q] << (4 * q);
            mo |= sho[base + q] << (4 * q);
        }
        int tileIdx = warp * 4 + lane;
        g_cmask[tileIdx * N_SESS + s] = mc;
        g_omask[tileIdx * N_SESS + s] = mo;
    }
}

// ---------------------------------------------------------------------------
// smooth_clamp(x,0,1), beta=100. Written so ptxas can fold |.| and -|.| into
// FFMA / MUFU source modifiers (no integer bit ops on the chain).
//   w  = 144.2695*(0.5 - |x-0.5|)
//   sp = max(w,0)*ln2/100 + poly4(2^(-|w|))   (abs err ~1e-6)
// ---------------------------------------------------------------------------
__device__ __forceinline__ float fast_clamp01(float x)
{
    float t  = x - 0.5f;
    float w  = fmaf(fabsf(t), -144.26950408889634f, 72.13475204444817f);
    float nw = -fabsf(w);
    float e;
    asm("ex2.approx.f32 %0, %1;" : "=f"(e) : "f"(nw));
    float m    = fmaxf(w, 0.0f);
    float e2   = e * e;
    float base = fmaf(m, 6.931471805599453e-3f, 1.4882e-6f);
    float low  = fmaf(9.9627e-3f, e, base);
    float hi   = fmaf(-5.5457e-4f, e, 2.1866e-3f);
    hi         = fmaf(hi, e, -4.6644e-3f);
    float sp   = fmaf(hi, e2, low);
    return (x < 0.5f) ? sp : 1.0f - sp;
}

// ---------------------------------------------------------------------------
// One 32-step tile. Coefficients selected from REGISTERS via FSEL (hoistable,
// off the serial chain). FIRST=true handles the t==0 alpha_first case.
// ---------------------------------------------------------------------------
struct Params {
    float a00, a01, a02, a03;
    float ga0, ga1, ga2, ga3;
    float gl0, gl1, gl2, gl3;
    float k0, k1, k2, k3;
};

template<bool FIRST>
__device__ __forceinline__ void do_tile(
    unsigned cm, unsigned om, const Params& P,
    float& QL, float& QR, float& lamL, float& lamR, float& alpha,
    float2 (*my)[34], int lane)
{
    #pragma unroll 16
    for (int i = 0; i < 32; ++i) {
        const bool pc = (cm >> i) & 1u;
        const bool po = (om >> i) & 1u;

        // register coefficient selects (predicates available a step early)
        float u01  = po ? P.k0 : P.k1;
        float u23  = po ? P.k2 : P.k3;
        float kL   = pc ? u01 : u23;
        float kR   = pc ? u23 : u01;
        float gl01 = po ? P.gl0 : P.gl1;
        float gl23 = po ? P.gl2 : P.gl3;
        float glL  = pc ? gl01 : gl23;
        float glR  = pc ? gl23 : gl01;
        float gaS  = pc ? (po ? P.ga0 : P.ga1) : (po ? P.ga2 : P.ga3);
        float a0S  = po ? P.a00 : P.a01;

        // alpha chain (critical): Q -> QS -> dS -> xa -> clamp -> an
        float QS   = pc ? QL   : QR;
        float lamS = pc ? lamL : lamR;
        float a1   = fmaf(-gaS, alpha, alpha);        // alpha*(1-gaS)
        float b2   = fmaf(gaS, a0S - lamS, a1);
        float xa   = fmaf(gaS, fabsf(u01 - QS), b2);
        float an   = fast_clamp01(xa);
        if (FIRST && i == 0)
            an = pc ? (po ? P.a00 : P.a01) : (po ? P.a02 : P.a03);

        // per-side signed diffs
        float diffL = kL - QL;
        float diffR = kR - QR;

        // lambda updates (old Q, old lam) — off the alpha chain
        float lamLn = fast_clamp01(fmaf(glL, fabsf(diffL) - lamL, lamL));
        float lamRn = fast_clamp01(fmaf(glR, fabsf(diffR) - lamR, lamR));

        // Q updates (old lam, new alpha)
        QL = fmaf(an, (1.0f - lamL) * diffL, QL);
        QR = fmaf(an, (1.0f - lamR) * diffR, QR);

        alpha = an;
        lamL  = lamLn;
        lamR  = lamRn;

        my[lane][i] = make_float2(QL, QR);
    }
}

// ---------------------------------------------------------------------------
// Main scan: one thread per session, block=32 (1 warp), grid=256 (>=148
// kills low-grid I$ throttle). Staging tile padded to 34 float2 (row stride
// 272 B, 16-aligned for the paired-row float4 flush).
// ---------------------------------------------------------------------------
__global__ __launch_bounds__(32)
void agent_kernel(const float* __restrict__ a0p, const float* __restrict__ gap,
                  const float* __restrict__ glp, const float* __restrict__ kvp,
                  float2* __restrict__ out)
{
    __shared__ __align__(16) float2 tile[32][34];

    Params P;
    P.a00 = a0p[0]; P.a01 = a0p[1]; P.a02 = a0p[2]; P.a03 = a0p[3];
    P.ga0 = gap[0]; P.ga1 = gap[1]; P.ga2 = gap[2]; P.ga3 = gap[3];
    P.gl0 = glp[0]; P.gl1 = glp[1]; P.gl2 = glp[2]; P.gl3 = glp[3];
    P.k0  = kvp[0]; P.k1  = kvp[1]; P.k2  = kvp[2]; P.k3  = kvp[3];

    const int lane  = threadIdx.x;                  // 0..31
    const int tid   = blockIdx.x * 32 + lane;       // session
    const int sbase = blockIdx.x * 32;

    float QL = 0.0f, QR = 0.0f;
    float lamL = 0.5f, lamR = 0.5f, alpha = 0.0f;

    unsigned cm = g_cmask[tid];
    unsigned om = g_omask[tid];

    const int half = lane >> 4;
    const int col  = (lane & 15) << 1;

    for (int w = 0; w < N_TILES; ++w) {
        unsigned cmn = 0, omn = 0;
        if (w + 1 < N_TILES) {
            cmn = g_cmask[(w + 1) * N_SESS + tid];
            omn = g_omask[(w + 1) * N_SESS + tid];
        }

        if (w == 0)
            do_tile<true >(cm, om, P, QL, QR, lamL, lamR, alpha, tile, lane);
        else
            do_tile<false>(cm, om, P, QL, QR, lamL, lamR, alpha, tile, lane);

        __syncwarp();
        // coalesced flush: pair rows, 128-bit LDS + STG
        const int tbase = w * 32;
        #pragma unroll
        for (int r = 0; r < 32; r += 2) {
            int row = r + half;
            float4 v = *reinterpret_cast<const float4*>(&tile[row][col]);
            *reinterpret_cast<float4*>(
                &out[(size_t)(sbase + row) * N_TRIALS + tbase + col]) = v;
        }
        __syncwarp();

        cm = cmn;
        om = omn;
    }
}

// ---------------------------------------------------------------------------
extern "C" void kernel_launch(void* const* d_in, const int* in_sizes, int n_in,
                              void* d_out, int out_size)
{
    (void)in_sizes; (void)n_in; (void)out_size;
    const float* input = (const float*)d_in[0];
    const float* a0    = (const float*)d_in[1];
    const float* ga    = (const float*)d_in[2];
    const float* gl    = (const float*)d_in[3];
    const float* kv    = (const float*)d_in[4];
    float2* out = (float2*)d_out;

    pack_kernel<<<N_SESS, 256>>>(input);
    agent_kernel<<<N_SESS / 32, 32>>>(a0, ga, gl, kv, out);
}

// round 7
// speedup vs baseline: 1.4190x; 1.0609x over previous
#include <cuda_runtime.h>
#include <cstdint>

#define N_SESS   8192
#define N_TRIALS 1024
#define N_TILES  32

// Packed masks, tile-major: mask[tile*N_SESS + session]
__device__ unsigned g_cmask[N_TILES * N_SESS];
__device__ unsigned g_omask[N_TILES * N_SESS];

// ---------------------------------------------------------------------------
// Pack kernel (validated): fully coalesced, block = one session.
// ---------------------------------------------------------------------------
__global__ __launch_bounds__(256) void pack_kernel(const float* __restrict__ in)
{
    __shared__ unsigned shc[256], sho[256];
    const int lane = threadIdx.x & 31;
    const int warp = threadIdx.x >> 5;     // 128-trial group, 0..7
    const int s    = blockIdx.x;           // session

    const float4* p = reinterpret_cast<const float4*>(
        in + (size_t)s * 3072 + warp * 384 + lane * 12);
    float4 v0 = p[0], v1 = p[1], v2 = p[2];

    unsigned nc = (unsigned)(v0.x > 0.5f)        | ((unsigned)(v0.w > 0.5f) << 1)
                | ((unsigned)(v1.z > 0.5f) << 2) | ((unsigned)(v2.y > 0.5f) << 3);
    unsigned no = (unsigned)(v0.z > 0.5f)        | ((unsigned)(v1.y > 0.5f) << 1)
                | ((unsigned)(v2.x > 0.5f) << 2) | ((unsigned)(v2.w > 0.5f) << 3);
    shc[threadIdx.x] = nc;
    sho[threadIdx.x] = no;
    __syncwarp();

    if (lane < 4) {
        int base = warp * 32 + lane * 8;
        unsigned mc = 0, mo = 0;
        #pragma unroll
        for (int q = 0; q < 8; ++q) {
            mc |= shc[base + q] << (4 * q);
            mo |= sho[base + q] << (4 * q);
        }
        int tileIdx = warp * 4 + lane;
        g_cmask[tileIdx * N_SESS + s] = mc;
        g_omask[tileIdx * N_SESS + s] = mo;
    }
}

// ---------------------------------------------------------------------------
// smooth_clamp(x,0,1), beta=100 (validated, rel_err ~5e-6 end to end).
// ---------------------------------------------------------------------------
__device__ __forceinline__ float fast_clamp01(float x)
{
    float t  = x - 0.5f;
    float w  = fmaf(fabsf(t), -144.26950408889634f, 72.13475204444817f);
    float nw = -fabsf(w);
    float e;
    asm("ex2.approx.f32 %0, %1;" : "=f"(e) : "f"(nw));
    float m    = fmaxf(w, 0.0f);
    float e2   = e * e;
    float base = fmaf(m, 6.931471805599453e-3f, 1.4882e-6f);
    float low  = fmaf(9.9627e-3f, e, base);
    float hi   = fmaf(-5.5457e-4f, e, 2.1866e-3f);
    hi         = fmaf(hi, e, -4.6644e-3f);
    float sp   = fmaf(hi, e2, low);
    return (x < 0.5f) ? sp : 1.0f - sp;
}

// ---------------------------------------------------------------------------
// One 32-step tile, slimmed:
//  - dS reuses diffL/diffR (when pc: kL==u01 so u01-QL == diffL; else diffR)
//  - momentum terms via single FMA: m = (1-lam)*diff = fmaf(-lam, diff, diff)
// ---------------------------------------------------------------------------
struct Params {
    float a00, a01, a02, a03;
    float ga0, ga1, ga2, ga3;
    float gl0, gl1, gl2, gl3;
    float k0, k1, k2, k3;
};

template<bool FIRST>
__device__ __forceinline__ void do_tile(
    unsigned cm, unsigned om, const Params& P,
    float& QL, float& QR, float& lamL, float& lamR, float& alpha,
    float2 (*my)[34], int lane)
{
    #pragma unroll 16
    for (int i = 0; i < 32; ++i) {
        const bool pc = (cm >> i) & 1u;
        const bool po = (om >> i) & 1u;

        // register coefficient selects (hoistable; predicates known early)
        float u01  = po ? P.k0 : P.k1;
        float u23  = po ? P.k2 : P.k3;
        float kL   = pc ? u01 : u23;
        float kR   = pc ? u23 : u01;
        float gl01 = po ? P.gl0 : P.gl1;
        float gl23 = po ? P.gl2 : P.gl3;
        float glL  = pc ? gl01 : gl23;
        float glR  = pc ? gl23 : gl01;
        float gaS  = pc ? (po ? P.ga0 : P.ga1) : (po ? P.ga2 : P.ga3);
        float a0S  = po ? P.a00 : P.a01;

        // per-side signed diffs (only depend on old Q)
        float diffL = kL - QL;
        float diffR = kR - QR;
        float diffS = pc ? diffL : diffR;        // chosen-side distance base
        float lamS  = pc ? lamL  : lamR;

        // alpha chain (critical): Q -> diff -> diffS -> xa -> clamp -> an
        float a1 = fmaf(-gaS, alpha, alpha);     // alpha*(1-gaS)
        float b2 = fmaf(gaS, a0S - lamS, a1);
        float xa = fmaf(gaS, fabsf(diffS), b2);
        float an = fast_clamp01(xa);
        if (FIRST && i == 0)
            an = pc ? (po ? P.a00 : P.a01) : (po ? P.a02 : P.a03);

        // lambda updates (old Q, old lam) — off the alpha chain
        float lamLn = fast_clamp01(fmaf(glL, fabsf(diffL) - lamL, lamL));
        float lamRn = fast_clamp01(fmaf(glR, fabsf(diffR) - lamR, lamR));

        // Q updates (old lam, new alpha); (1-lam)*diff as one FMA
        float mL = fmaf(-lamL, diffL, diffL);
        float mR = fmaf(-lamR, diffR, diffR);
        QL = fmaf(an, mL, QL);
        QR = fmaf(an, mR, QR);

        alpha = an;
        lamL  = lamLn;
        lamR  = lamRn;

        my[lane][i] = make_float2(QL, QR);
    }
}

// ---------------------------------------------------------------------------
// Main scan: one thread per session. block=128 -> warps land on SMSP 0..3
// (exactly one warp per SMSP, no scheduler contention). grid=64.
// Staging tile padded to 34 float2 (row stride 272 B, 16-aligned).
// ---------------------------------------------------------------------------
__global__ __launch_bounds__(128, 1)
void agent_kernel(const float* __restrict__ a0p, const float* __restrict__ gap,
                  const float* __restrict__ glp, const float* __restrict__ kvp,
                  float2* __restrict__ out)
{
    __shared__ __align__(16) float2 tile[4][32][34];

    Params P;
    P.a00 = a0p[0]; P.a01 = a0p[1]; P.a02 = a0p[2]; P.a03 = a0p[3];
    P.ga0 = gap[0]; P.ga1 = gap[1]; P.ga2 = gap[2]; P.ga3 = gap[3];
    P.gl0 = glp[0]; P.gl1 = glp[1]; P.gl2 = glp[2]; P.gl3 = glp[3];
    P.k0  = kvp[0]; P.k1  = kvp[1]; P.k2  = kvp[2]; P.k3  = kvp[3];

    const int lane  = threadIdx.x & 31;
    const int warp  = threadIdx.x >> 5;
    const int wg    = blockIdx.x * 4 + warp;        // global warp id
    const int sbase = wg * 32;                      // warp's first session
    const int tid   = sbase + lane;                 // this thread's session
    float2 (*my)[34] = tile[warp];

    float QL = 0.0f, QR = 0.0f;
    float lamL = 0.5f, lamR = 0.5f, alpha = 0.0f;

    unsigned cm = g_cmask[tid];
    unsigned om = g_omask[tid];

    const int half = lane >> 4;
    const int col  = (lane & 15) << 1;

    for (int w = 0; w < N_TILES; ++w) {
        unsigned cmn = 0, omn = 0;
        if (w + 1 < N_TILES) {
            cmn = g_cmask[(w + 1) * N_SESS + tid];
            omn = g_omask[(w + 1) * N_SESS + tid];
        }

        if (w == 0)
            do_tile<true >(cm, om, P, QL, QR, lamL, lamR, alpha, my, lane);
        else
            do_tile<false>(cm, om, P, QL, QR, lamL, lamR, alpha, my, lane);

        __syncwarp();
        // coalesced flush: pair rows, 128-bit LDS + STG
        const int tbase = w * 32;
        #pragma unroll
        for (int r = 0; r < 32; r += 2) {
            int row = r + half;
            float4 v = *reinterpret_cast<const float4*>(&my[row][col]);
            *reinterpret_cast<float4*>(
                &out[(size_t)(sbase + row) * N_TRIALS + tbase + col]) = v;
        }
        __syncwarp();

        cm = cmn;
        om = omn;
    }
}

// ---------------------------------------------------------------------------
extern "C" void kernel_launch(void* const* d_in, const int* in_sizes, int n_in,
                              void* d_out, int out_size)
{
    (void)in_sizes; (void)n_in; (void)out_size;
    const float* input = (const float*)d_in[0];
    const float* a0    = (const float*)d_in[1];
    const float* ga    = (const float*)d_in[2];
    const float* gl    = (const float*)d_in[3];
    const float* kv    = (const float*)d_in[4];
    float2* out = (float2*)d_out;

    pack_kernel<<<N_SESS, 256>>>(input);
    agent_kernel<<<N_SESS / 128, 128>>>(a0, ga, gl, kv, out);
}